// round 4
// baseline (speedup 1.0000x reference)
#include <cuda_runtime.h>
#include <math.h>

#define NNODE 100000
#define DDIM  256
#define DV4   64          // DDIM/4
#define NL    3           // accumulated layers 1..3
#define FEAT  64          // pairwise feature dim (8x8)
#define HID   256         // MLP hidden
#define TP    8           // pairs per block in pairwise kernel
#define WDECAY 1e-06f

// Scratch: scatter accumulators for layers 1..3 (base decay*rp folded in at gather time)
__device__ __align__(16) float g_acc[(size_t)NL * NNODE * DDIM];   // 307 MB, zero-init per launch
__device__ unsigned char g_qmask[NNODE];

// ---------------------------------------------------------------------------
// Kernel 1: zero scratch + query mask
// ---------------------------------------------------------------------------
__global__ void zero_kernel() {
    const size_t total4 = (size_t)NL * NNODE * DDIM / 4;
    float4* p = (float4*)g_acc;
    const size_t stride = (size_t)gridDim.x * blockDim.x;
    size_t i0 = (size_t)blockIdx.x * blockDim.x + threadIdx.x;
    float4 z = make_float4(0.f, 0.f, 0.f, 0.f);
    for (size_t i = i0; i < total4; i += stride) p[i] = z;
    for (size_t i = i0; i < NNODE; i += stride) g_qmask[i] = 0;
}

// ---------------------------------------------------------------------------
// Kernel 2: mark nodes that appear in any query pair
// ---------------------------------------------------------------------------
__global__ void mask_kernel(const int* __restrict__ qs, const int* __restrict__ qd, int B) {
    int i = blockIdx.x * blockDim.x + threadIdx.x;
    if (i < B) {
        g_qmask[qs[i]] = 1;
        g_qmask[qd[i]] = 1;
    }
}

// ---------------------------------------------------------------------------
// Kernel 3: scatter. One warp per (edge, layer). Layers independent (gathers
// read the pre-update decayed tables = scalar * original rp tables).
//   acc[layer][src] += decay^layer * tw[e] * rp_layer[dst]   (and symmetric)
// Only scatter into rows that a query will read (g_qmask).
// ---------------------------------------------------------------------------
__global__ void scatter_kernel(const float* __restrict__ rp0,
                               const float* __restrict__ rp1,
                               const float* __restrict__ rp2,
                               const float* __restrict__ times,
                               const float* __restrict__ now_time,
                               const int*   __restrict__ src_ids,
                               const int*   __restrict__ dst_ids,
                               int E) {
    int gtid = blockIdx.x * blockDim.x + threadIdx.x;
    int wid  = gtid >> 5;
    int lane = threadIdx.x & 31;
    int ntask = E * NL;
    if (wid >= ntask) return;

    int e     = wid / 3;
    int layer = wid - e * 3;        // 0..2 -> writes acc layer (layer), reads rp(layer)

    float nextt = __ldg(&times[E - 1]);
    float decay = expf(-WDECAY * (nextt - __ldg(&now_time[0])));
    float c = expf(-WDECAY * (nextt - __ldg(&times[e])));   // tw[e]
    if (layer >= 1) c *= decay;
    if (layer == 2) c *= decay;

    const float* rp = (layer == 0) ? rp0 : ((layer == 1) ? rp1 : rp2);
    const float4* rp4 = (const float4*)rp;
    float4* acc4 = ((float4*)g_acc) + (size_t)layer * NNODE * DV4;

    int s = __ldg(&src_ids[e]);
    int d = __ldg(&dst_ids[e]);
    bool ms = g_qmask[s] != 0;
    bool md = g_qmask[d] != 0;

    if (ms) {
        const float4* r = rp4 + (size_t)d * DV4;
        float4* a = acc4 + (size_t)s * DV4;
        #pragma unroll
        for (int k = lane; k < DV4; k += 32) {
            float4 v = r[k];
            asm volatile("red.global.add.v4.f32 [%0], {%1,%2,%3,%4};"
                         :: "l"(a + k), "f"(v.x * c), "f"(v.y * c), "f"(v.z * c), "f"(v.w * c)
                         : "memory");
        }
    }
    if (md) {
        const float4* r = rp4 + (size_t)s * DV4;
        float4* a = acc4 + (size_t)d * DV4;
        #pragma unroll
        for (int k = lane; k < DV4; k += 32) {
            float4 v = r[k];
            asm volatile("red.global.add.v4.f32 [%0], {%1,%2,%3,%4};"
                         :: "l"(a + k), "f"(v.x * c), "f"(v.y * c), "f"(v.z * c), "f"(v.w * c)
                         : "memory");
        }
    }
}

// ---------------------------------------------------------------------------
// Kernel 4: pairwise feature + MLP. TP pairs per 256-thread block.
//  proj[r][k]: r=0..3 src layers, r=4..7 dst layers; new_l = decay^l*rp_l + acc_l
//  gram -> log1p(relu) -> feat[64] -> relu(feat@w1+b1) -> h@w2+b2
// ---------------------------------------------------------------------------
__global__ void pairwise_kernel(const float* __restrict__ rp0,
                                const float* __restrict__ rp1,
                                const float* __restrict__ rp2,
                                const float* __restrict__ rp3,
                                const float* __restrict__ times,
                                const float* __restrict__ now_time,
                                const float* __restrict__ w1,
                                const float* __restrict__ b1,
                                const float* __restrict__ w2,
                                const float* __restrict__ b2,
                                const int*   __restrict__ qs,
                                const int*   __restrict__ qd,
                                float* __restrict__ out,
                                int B, int E) {
    __shared__ __align__(16) float proj[8 * 260];     // pitch 260 floats; reused as h (pitch 257)
    __shared__ float feat[TP * 68];
    __shared__ float gpart[4 * 64];
    __shared__ float opart[4 * TP * 64];

    const int tid = threadIdx.x;
    const int pb  = blockIdx.x * TP;

    float nextt = times[E - 1];
    float decay = expf(-WDECAY * (nextt - now_time[0]));
    const float sc1 = decay, sc2 = decay * decay, sc3 = sc2 * decay;
    const float scl[4] = {1.f, sc1, sc2, sc3};
    const float* rp[4] = {rp0, rp1, rp2, rp3};

    const int pq = tid & 63;
    const int cc = tid >> 6;
    const int p  = pq >> 3;
    const int q  = pq & 7;

    for (int t = 0; t < TP; t++) {
        int pi = pb + t;
        if (pi < B) {
            int s = qs[pi], d = qd[pi];
            int k = tid;      // 0..255 == DDIM
            #pragma unroll
            for (int l = 0; l < 4; l++) {
                float vs = rp[l][(size_t)s * DDIM + k] * scl[l];
                float vd = rp[l][(size_t)d * DDIM + k] * scl[l];
                if (l > 0) {
                    vs += g_acc[(size_t)(l - 1) * NNODE * DDIM + (size_t)s * DDIM + k];
                    vd += g_acc[(size_t)(l - 1) * NNODE * DDIM + (size_t)d * DDIM + k];
                }
                proj[l * 260 + k]       = vs;
                proj[(4 + l) * 260 + k] = vd;
            }
            __syncthreads();
            // gram partials: thread (pq, cc) does 64 k-values (16 float4)
            const float4* A  = (const float4*)(proj + p * 260);
            const float4* Bv = (const float4*)(proj + q * 260);
            float sx = 0.f, sy = 0.f, sz = 0.f, sw = 0.f;
            #pragma unroll
            for (int kk = 0; kk < 16; kk++) {
                float4 a = A[cc * 16 + kk];
                float4 b = Bv[cc * 16 + kk];
                sx += a.x * b.x; sy += a.y * b.y;
                sz += a.z * b.z; sw += a.w * b.w;
            }
            gpart[cc * 64 + pq] = (sx + sy) + (sz + sw);
            __syncthreads();
            if (tid < 64) {
                float g = gpart[tid] + gpart[64 + tid] + gpart[128 + tid] + gpart[192 + tid];
                feat[t * 68 + tid] = log1pf(fmaxf(g, 0.f));
            }
            __syncthreads();
        }
    }

    // MLP layer 1: thread j computes h[t][j] for all TP pairs
    float h[TP];
    #pragma unroll
    for (int t = 0; t < TP; t++) h[t] = 0.f;
    const int j = tid;
    #pragma unroll 4
    for (int f = 0; f < FEAT; f++) {
        float w = __ldg(&w1[f * HID + j]);
        #pragma unroll
        for (int t = 0; t < TP; t++) h[t] += feat[t * 68 + f] * w;
    }
    float bb = __ldg(&b1[j]);
    #pragma unroll
    for (int t = 0; t < TP; t++) h[t] = fmaxf(h[t] + bb, 0.f);

    // stage h into shared (reuse proj buffer, pitch 257 to avoid conflicts)
    #pragma unroll
    for (int t = 0; t < TP; t++) proj[t * 257 + j] = h[t];
    __syncthreads();

    // MLP layer 2: thread (fo, cj) computes partial over 64 j-values
    const int fo = tid & 63;
    const int cj = tid >> 6;
    float o[TP];
    #pragma unroll
    for (int t = 0; t < TP; t++) o[t] = 0.f;
    #pragma unroll 4
    for (int jj = 0; jj < 64; jj++) {
        int jx = cj * 64 + jj;
        float w = __ldg(&w2[jx * FEAT + fo]);
        #pragma unroll
        for (int t = 0; t < TP; t++) o[t] += proj[t * 257 + jx] * w;
    }
    #pragma unroll
    for (int t = 0; t < TP; t++) opart[(cj * TP + t) * 64 + fo] = o[t];
    __syncthreads();

    for (int idx = tid; idx < TP * 64; idx += 256) {
        int t = idx >> 6, ff = idx & 63;
        int pi = pb + t;
        if (pi < B) {
            float v = __ldg(&b2[ff])
                    + opart[(0 * TP + t) * 64 + ff]
                    + opart[(1 * TP + t) * 64 + ff]
                    + opart[(2 * TP + t) * 64 + ff]
                    + opart[(3 * TP + t) * 64 + ff];
            out[(size_t)pi * FEAT + ff] = v;
        }
    }
}

// ---------------------------------------------------------------------------
extern "C" void kernel_launch(void* const* d_in, const int* in_sizes, int n_in,
                              void* d_out, int out_size) {
    const float* rp0  = (const float*)d_in[0];
    const float* rp1  = (const float*)d_in[1];
    const float* rp2  = (const float*)d_in[2];
    const float* rp3  = (const float*)d_in[3];
    const float* times = (const float*)d_in[4];
    const float* nowt  = (const float*)d_in[5];
    const float* w1   = (const float*)d_in[6];
    const float* b1   = (const float*)d_in[7];
    const float* w2   = (const float*)d_in[8];
    const float* b2   = (const float*)d_in[9];
    const int* src    = (const int*)d_in[10];
    const int* dst    = (const int*)d_in[11];
    const int* qsrc   = (const int*)d_in[12];
    const int* qdst   = (const int*)d_in[13];
    float* out = (float*)d_out;

    int E = in_sizes[4];
    int B = in_sizes[12];

    zero_kernel<<<2048, 256>>>();
    mask_kernel<<<(B + 255) / 256, 256>>>(qsrc, qdst, B);

    int ntask = E * NL;                      // warps
    int sblocks = (ntask + 7) / 8;           // 8 warps / block
    scatter_kernel<<<sblocks, 256>>>(rp0, rp1, rp2, times, nowt, src, dst, E);

    int pblocks = (B + TP - 1) / TP;
    pairwise_kernel<<<pblocks, 256>>>(rp0, rp1, rp2, rp3, times, nowt,
                                      w1, b1, w2, b2, qsrc, qdst, out, B, E);
}

// round 8
// speedup vs baseline: 1.0385x; 1.0385x over previous
#include <cuda_runtime.h>
#include <math.h>

#define NNODE 100000
#define DDIM  256
#define DV4   64          // DDIM/4
#define NL    3           // accumulated layers 1..3
#define FEAT  64          // pairwise feature dim (8x8)
#define HID   256         // MLP hidden
#define TP    8           // pairs per block in pairwise kernel
#define WDECAY 1e-06f

// Scratch: scatter accumulators for layers 1..3 (base decay*rp folded in at gather time)
__device__ __align__(16) float g_acc[(size_t)NL * NNODE * DDIM];   // 307 MB
__device__ unsigned char g_qmask[NNODE];

// idx (0..35) -> (p,q) with p<=q for the 8x8 symmetric gram
__constant__ int c_p36[36] = {0,0,0,0,0,0,0,0, 1,1,1,1,1,1,1, 2,2,2,2,2,2, 3,3,3,3,3, 4,4,4,4, 5,5,5, 6,6, 7};
__constant__ int c_q36[36] = {0,1,2,3,4,5,6,7, 1,2,3,4,5,6,7, 2,3,4,5,6,7, 3,4,5,6,7, 4,5,6,7, 5,6,7, 6,7, 7};

// ---- packed f32x2 helpers (Blackwell) ----
__device__ __forceinline__ unsigned long long pk2(float a, float b) {
    unsigned long long r;
    asm("mov.b64 %0, {%1,%2};" : "=l"(r) : "f"(a), "f"(b));
    return r;
}
__device__ __forceinline__ void fma2(unsigned long long& d, unsigned long long a, unsigned long long b) {
    asm("fma.rn.f32x2 %0, %1, %2, %0;" : "+l"(d) : "l"(a), "l"(b));
}
__device__ __forceinline__ void upk2(float& lo, float& hi, unsigned long long v) {
    asm("mov.b64 {%0,%1}, %2;" : "=f"(lo), "=f"(hi) : "l"(v));
}

// ---------------------------------------------------------------------------
// Kernel 0: clear query mask
// ---------------------------------------------------------------------------
__global__ void clear_mask_kernel() {
    int i = blockIdx.x * blockDim.x + threadIdx.x;
    if (i < NNODE) g_qmask[i] = 0;
}

// ---------------------------------------------------------------------------
// Kernel 1: mark nodes that appear in any query pair
// ---------------------------------------------------------------------------
__global__ void mask_kernel(const int* __restrict__ qs, const int* __restrict__ qd, int B) {
    int i = blockIdx.x * blockDim.x + threadIdx.x;
    if (i < B) {
        g_qmask[qs[i]] = 1;
        g_qmask[qd[i]] = 1;
    }
}

// ---------------------------------------------------------------------------
// Kernel 2: zero only the acc rows that will be read (masked nodes)
// ---------------------------------------------------------------------------
__global__ void zero_masked_kernel() {
    const size_t total = (size_t)NNODE * DV4;
    const size_t stride = (size_t)gridDim.x * blockDim.x;
    float4 z = make_float4(0.f, 0.f, 0.f, 0.f);
    float4* acc4 = (float4*)g_acc;
    for (size_t i = (size_t)blockIdx.x * blockDim.x + threadIdx.x; i < total; i += stride) {
        size_t n = i >> 6;
        if (g_qmask[n]) {
            size_t c = i & 63;
            acc4[0 * (size_t)NNODE * DV4 + n * DV4 + c] = z;
            acc4[1 * (size_t)NNODE * DV4 + n * DV4 + c] = z;
            acc4[2 * (size_t)NNODE * DV4 + n * DV4 + c] = z;
        }
    }
}

// ---------------------------------------------------------------------------
// Kernel 3: scatter. One warp per (edge, layer). Layers independent (gathers
// read the pre-update decayed tables = scalar * original rp tables).
//   acc[layer][src] += decay^layer * tw[e] * rp_layer[dst]   (and symmetric)
// Only scatter into rows that a query will read (g_qmask).
// ---------------------------------------------------------------------------
__global__ void scatter_kernel(const float* __restrict__ rp0,
                               const float* __restrict__ rp1,
                               const float* __restrict__ rp2,
                               const float* __restrict__ times,
                               const float* __restrict__ now_time,
                               const int*   __restrict__ src_ids,
                               const int*   __restrict__ dst_ids,
                               int E) {
    int gtid = blockIdx.x * blockDim.x + threadIdx.x;
    int wid  = gtid >> 5;
    int lane = threadIdx.x & 31;
    int ntask = E * NL;
    if (wid >= ntask) return;

    int e     = wid / 3;
    int layer = wid - e * 3;

    float nextt = __ldg(&times[E - 1]);
    float decay = expf(-WDECAY * (nextt - __ldg(&now_time[0])));
    float c = expf(-WDECAY * (nextt - __ldg(&times[e])));   // tw[e]
    if (layer >= 1) c *= decay;
    if (layer == 2) c *= decay;

    const float* rp = (layer == 0) ? rp0 : ((layer == 1) ? rp1 : rp2);
    const float4* rp4 = (const float4*)rp;
    float4* acc4 = ((float4*)g_acc) + (size_t)layer * NNODE * DV4;

    int s = __ldg(&src_ids[e]);
    int d = __ldg(&dst_ids[e]);
    bool ms = g_qmask[s] != 0;
    bool md = g_qmask[d] != 0;

    if (ms) {
        const float4* r = rp4 + (size_t)d * DV4;
        float4* a = acc4 + (size_t)s * DV4;
        #pragma unroll
        for (int k = lane; k < DV4; k += 32) {
            float4 v = r[k];
            asm volatile("red.global.add.v4.f32 [%0], {%1,%2,%3,%4};"
                         :: "l"(a + k), "f"(v.x * c), "f"(v.y * c), "f"(v.z * c), "f"(v.w * c)
                         : "memory");
        }
    }
    if (md) {
        const float4* r = rp4 + (size_t)s * DV4;
        float4* a = acc4 + (size_t)d * DV4;
        #pragma unroll
        for (int k = lane; k < DV4; k += 32) {
            float4 v = r[k];
            asm volatile("red.global.add.v4.f32 [%0], {%1,%2,%3,%4};"
                         :: "l"(a + k), "f"(v.x * c), "f"(v.y * c), "f"(v.z * c), "f"(v.w * c)
                         : "memory");
        }
    }
}

// ---------------------------------------------------------------------------
// Kernel 4: pairwise feature + MLP.
// Warp-per-pair register-resident gram (symmetric, 36 entries) + butterfly
// reduce; MLP with f32x2 packed FMAs over the t (pair) dimension.
// ---------------------------------------------------------------------------
__global__ __launch_bounds__(256)
void pairwise_kernel(const float* __restrict__ rp0,
                     const float* __restrict__ rp1,
                     const float* __restrict__ rp2,
                     const float* __restrict__ rp3,
                     const float* __restrict__ times,
                     const float* __restrict__ now_time,
                     const float* __restrict__ w1,
                     const float* __restrict__ b1,
                     const float* __restrict__ w2,
                     const float* __restrict__ b2,
                     const int*   __restrict__ qs,
                     const int*   __restrict__ qd,
                     float* __restrict__ out,
                     int B, int E) {
    __shared__ float gram_s[TP * 36];                       // [t][36]
    __shared__ __align__(16) float feat_s[FEAT * TP];       // [f][t], t contiguous
    __shared__ __align__(16) float h_s[HID * 12];           // [j][t] pitch 12 (bank-safe)
    __shared__ float opart[4 * TP * 64];

    const int tid  = threadIdx.x;
    const int lane = tid & 31;
    const int wrp  = tid >> 5;                              // 0..7 == t
    const int pb   = blockIdx.x * TP;
    const int pi   = pb + wrp;

    float nextt = times[E - 1];
    float decay = expf(-WDECAY * (nextt - now_time[0]));
    const float sc1 = decay, sc2 = decay * decay, sc3 = sc2 * decay;
    const float scl[4] = {1.f, sc1, sc2, sc3};

    // ---- Phase 1: per-warp gram (36 symmetric entries) ----
    if (pi < B) {
        int s = qs[pi], d = qd[pi];
        const float4* rp4[4] = {(const float4*)rp0, (const float4*)rp1,
                                (const float4*)rp2, (const float4*)rp3};
        const float4* acc4 = (const float4*)g_acc;

        float g[36];
        #pragma unroll
        for (int i = 0; i < 36; i++) g[i] = 0.f;

        #pragma unroll
        for (int c = 0; c < 2; c++) {
            int cs = (int)(lane * 2 + c);
            float4 v[8];
            #pragma unroll
            for (int l = 0; l < 4; l++) {
                float4 a = rp4[l][(size_t)s * DV4 + cs];
                float4 b = rp4[l][(size_t)d * DV4 + cs];
                a.x *= scl[l]; a.y *= scl[l]; a.z *= scl[l]; a.w *= scl[l];
                b.x *= scl[l]; b.y *= scl[l]; b.z *= scl[l]; b.w *= scl[l];
                if (l > 0) {
                    float4 ea = acc4[(size_t)(l - 1) * NNODE * DV4 + (size_t)s * DV4 + cs];
                    float4 eb = acc4[(size_t)(l - 1) * NNODE * DV4 + (size_t)d * DV4 + cs];
                    a.x += ea.x; a.y += ea.y; a.z += ea.z; a.w += ea.w;
                    b.x += eb.x; b.y += eb.y; b.z += eb.z; b.w += eb.w;
                }
                v[l] = a;
                v[4 + l] = b;
            }
            int idx = 0;
            #pragma unroll
            for (int p = 0; p < 8; p++) {
                #pragma unroll
                for (int q = p; q < 8; q++) {
                    float4 a = v[p], b = v[q];
                    g[idx] = fmaf(a.x, b.x, fmaf(a.y, b.y, fmaf(a.z, b.z, fmaf(a.w, b.w, g[idx]))));
                    idx++;
                }
            }
        }
        // butterfly reduce each entry over lanes
        #pragma unroll
        for (int i = 0; i < 36; i++) {
            #pragma unroll
            for (int st = 16; st > 0; st >>= 1)
                g[i] += __shfl_xor_sync(0xffffffffu, g[i], st);
        }
        // scatter 36 sums to shared (one owning lane per entry; static reg index)
        #pragma unroll
        for (int i = 0; i < 36; i++) {
            if (lane == (i & 31)) gram_s[wrp * 36 + i] = g[i];
        }
    }
    __syncthreads();

    // ---- Phase 2: log1p + symmetric expand into feat_s[f][t] ----
    for (int e = tid; e < TP * 36; e += 256) {
        int t = e / 36, i = e - t * 36;
        int p = c_p36[i], q = c_q36[i];
        float val = log1pf(fmaxf(gram_s[t * 36 + i], 0.f));
        feat_s[(p * 8 + q) * TP + t] = val;
        feat_s[(q * 8 + p) * TP + t] = val;
    }
    __syncthreads();

    // ---- MLP layer 1 (f32x2 packed over t) ----
    {
        const int j = tid;
        unsigned long long hp0 = 0ull, hp1 = 0ull, hp2 = 0ull, hp3 = 0ull;
        #pragma unroll 4
        for (int f = 0; f < FEAT; f++) {
            const ulonglong2* fp = (const ulonglong2*)(feat_s + f * TP);
            ulonglong2 fa = fp[0];     // (t0,t1),(t2,t3)
            ulonglong2 fb = fp[1];     // (t4,t5),(t6,t7)
            float w = __ldg(&w1[f * HID + j]);
            unsigned long long ww = pk2(w, w);
            fma2(hp0, fa.x, ww);
            fma2(hp1, fa.y, ww);
            fma2(hp2, fb.x, ww);
            fma2(hp3, fb.y, ww);
        }
        float bb = __ldg(&b1[j]);
        float h0, h1, h2, h3, h4, h5, h6, h7;
        upk2(h0, h1, hp0); upk2(h2, h3, hp1); upk2(h4, h5, hp2); upk2(h6, h7, hp3);
        h0 = fmaxf(h0 + bb, 0.f); h1 = fmaxf(h1 + bb, 0.f);
        h2 = fmaxf(h2 + bb, 0.f); h3 = fmaxf(h3 + bb, 0.f);
        h4 = fmaxf(h4 + bb, 0.f); h5 = fmaxf(h5 + bb, 0.f);
        h6 = fmaxf(h6 + bb, 0.f); h7 = fmaxf(h7 + bb, 0.f);
        float4* hs = (float4*)(h_s + j * 12);
        hs[0] = make_float4(h0, h1, h2, h3);
        hs[1] = make_float4(h4, h5, h6, h7);
    }
    __syncthreads();

    // ---- MLP layer 2 (f32x2 packed over t) ----
    {
        const int fo = tid & 63;
        const int cj = tid >> 6;
        unsigned long long op0 = 0ull, op1 = 0ull, op2 = 0ull, op3 = 0ull;
        #pragma unroll 4
        for (int jj = 0; jj < 64; jj++) {
            int jx = cj * 64 + jj;
            const ulonglong2* hp = (const ulonglong2*)(h_s + jx * 12);
            ulonglong2 ha = hp[0];
            ulonglong2 hb = hp[1];
            float w = __ldg(&w2[jx * FEAT + fo]);
            unsigned long long ww = pk2(w, w);
            fma2(op0, ha.x, ww);
            fma2(op1, ha.y, ww);
            fma2(op2, hb.x, ww);
            fma2(op3, hb.y, ww);
        }
        float o0, o1, o2, o3, o4, o5, o6, o7;
        upk2(o0, o1, op0); upk2(o2, o3, op1); upk2(o4, o5, op2); upk2(o6, o7, op3);
        opart[(cj * TP + 0) * 64 + fo] = o0;
        opart[(cj * TP + 1) * 64 + fo] = o1;
        opart[(cj * TP + 2) * 64 + fo] = o2;
        opart[(cj * TP + 3) * 64 + fo] = o3;
        opart[(cj * TP + 4) * 64 + fo] = o4;
        opart[(cj * TP + 5) * 64 + fo] = o5;
        opart[(cj * TP + 6) * 64 + fo] = o6;
        opart[(cj * TP + 7) * 64 + fo] = o7;
    }
    __syncthreads();

    for (int idx = tid; idx < TP * 64; idx += 256) {
        int t = idx >> 6, ff = idx & 63;
        int po = pb + t;
        if (po < B) {
            float v = __ldg(&b2[ff])
                    + opart[(0 * TP + t) * 64 + ff]
                    + opart[(1 * TP + t) * 64 + ff]
                    + opart[(2 * TP + t) * 64 + ff]
                    + opart[(3 * TP + t) * 64 + ff];
            out[(size_t)po * FEAT + ff] = v;
        }
    }
}

// ---------------------------------------------------------------------------
extern "C" void kernel_launch(void* const* d_in, const int* in_sizes, int n_in,
                              void* d_out, int out_size) {
    const float* rp0  = (const float*)d_in[0];
    const float* rp1  = (const float*)d_in[1];
    const float* rp2  = (const float*)d_in[2];
    const float* rp3  = (const float*)d_in[3];
    const float* times = (const float*)d_in[4];
    const float* nowt  = (const float*)d_in[5];
    const float* w1   = (const float*)d_in[6];
    const float* b1   = (const float*)d_in[7];
    const float* w2   = (const float*)d_in[8];
    const float* b2   = (const float*)d_in[9];
    const int* src    = (const int*)d_in[10];
    const int* dst    = (const int*)d_in[11];
    const int* qsrc   = (const int*)d_in[12];
    const int* qdst   = (const int*)d_in[13];
    float* out = (float*)d_out;

    int E = in_sizes[4];
    int B = in_sizes[12];

    clear_mask_kernel<<<(NNODE + 255) / 256, 256>>>();
    mask_kernel<<<(B + 255) / 256, 256>>>(qsrc, qdst, B);
    zero_masked_kernel<<<4096, 256>>>();

    int ntask = E * NL;                      // warps
    int sblocks = (ntask + 7) / 8;           // 8 warps / block
    scatter_kernel<<<sblocks, 256>>>(rp0, rp1, rp2, times, nowt, src, dst, E);

    int pblocks = (B + TP - 1) / TP;
    pairwise_kernel<<<pblocks, 256>>>(rp0, rp1, rp2, rp3, times, nowt,
                                      w1, b1, w2, b2, qsrc, qdst, out, B, E);
}

// round 9
// speedup vs baseline: 1.1768x; 1.1332x over previous
#include <cuda_runtime.h>
#include <math.h>

#define NNODE 100000
#define DDIM  256
#define DV4   64          // DDIM/4
#define NL    3           // accumulated layers 1..3
#define FEAT  64          // pairwise feature dim (8x8)
#define HID   256         // MLP hidden
#define TP    8           // pairs per block in pairwise kernel
#define WDECAY 1e-06f
#define EMAX  200000
#define NSCB  1024        // scan block width
#define NB_SCAN ((NNODE + NSCB - 1) / NSCB)

// Scratch: per-layer accumulators (base decay^l*rp_l folded in at pairwise gather)
__device__ __align__(16) float g_acc[(size_t)NL * NNODE * DDIM];   // 307 MB
__device__ unsigned char g_qmask[NNODE];

// CSR adjacency (only masked endpoints get entries)
__device__ int   g_cnt[NNODE];
__device__ int   g_off[NNODE];
__device__ int   g_cur[NNODE];
__device__ int   g_bsum[NB_SCAN + 1];
__device__ int   g_bsumx[NB_SCAN + 1];
__device__ int   g_adj[2 * EMAX];
__device__ float g_w[2 * EMAX];

// idx (0..35) -> (p,q) with p<=q for the 8x8 symmetric gram
__constant__ int c_p36[36] = {0,0,0,0,0,0,0,0, 1,1,1,1,1,1,1, 2,2,2,2,2,2, 3,3,3,3,3, 4,4,4,4, 5,5,5, 6,6, 7};
__constant__ int c_q36[36] = {0,1,2,3,4,5,6,7, 1,2,3,4,5,6,7, 2,3,4,5,6,7, 3,4,5,6,7, 4,5,6,7, 5,6,7, 6,7, 7};

// ---- packed f32x2 helpers (Blackwell) ----
__device__ __forceinline__ unsigned long long pk2(float a, float b) {
    unsigned long long r;
    asm("mov.b64 %0, {%1,%2};" : "=l"(r) : "f"(a), "f"(b));
    return r;
}
__device__ __forceinline__ void fma2(unsigned long long& d, unsigned long long a, unsigned long long b) {
    asm("fma.rn.f32x2 %0, %1, %2, %0;" : "+l"(d) : "l"(a), "l"(b));
}
__device__ __forceinline__ void upk2(float& lo, float& hi, unsigned long long v) {
    asm("mov.b64 {%0,%1}, %2;" : "=f"(lo), "=f"(hi) : "l"(v));
}

// ---------------------------------------------------------------------------
// Setup: clear qmask + per-node counters
// ---------------------------------------------------------------------------
__global__ void setup_kernel() {
    int i = blockIdx.x * blockDim.x + threadIdx.x;
    if (i < NNODE) { g_qmask[i] = 0; g_cnt[i] = 0; }
}

__global__ void mask_kernel(const int* __restrict__ qs, const int* __restrict__ qd, int B) {
    int i = blockIdx.x * blockDim.x + threadIdx.x;
    if (i < B) {
        g_qmask[qs[i]] = 1;
        g_qmask[qd[i]] = 1;
    }
}

// ---------------------------------------------------------------------------
// CSR build: histogram -> scan -> fill
// ---------------------------------------------------------------------------
__global__ void hist_kernel(const int* __restrict__ src, const int* __restrict__ dst, int E) {
    int e = blockIdx.x * blockDim.x + threadIdx.x;
    if (e < E) {
        int s = src[e], d = dst[e];
        if (g_qmask[s]) atomicAdd(&g_cnt[s], 1);
        if (g_qmask[d]) atomicAdd(&g_cnt[d], 1);
    }
}

__global__ void scanA_kernel() {
    __shared__ int sh[NSCB];
    int tid = threadIdx.x;
    int i = blockIdx.x * NSCB + tid;
    int v = (i < NNODE) ? g_cnt[i] : 0;
    sh[tid] = v;
    __syncthreads();
    #pragma unroll
    for (int st = 1; st < NSCB; st <<= 1) {
        int t = (tid >= st) ? sh[tid - st] : 0;
        __syncthreads();
        sh[tid] += t;
        __syncthreads();
    }
    if (i < NNODE) g_off[i] = sh[tid] - v;     // exclusive within block
    if (tid == NSCB - 1) g_bsum[blockIdx.x] = sh[tid];
}

__global__ void scanB_kernel() {
    if (threadIdx.x == 0 && blockIdx.x == 0) {
        int run = 0;
        for (int b = 0; b < NB_SCAN; b++) {
            int t = g_bsum[b];
            g_bsumx[b] = run;
            run += t;
        }
    }
}

__global__ void scanC_kernel() {
    int i = blockIdx.x * blockDim.x + threadIdx.x;
    if (i < NNODE) {
        int o = g_off[i] + g_bsumx[i >> 10];
        g_off[i] = o;
        g_cur[i] = o;
    }
}

__global__ void fill_kernel(const int* __restrict__ src, const int* __restrict__ dst,
                            const float* __restrict__ times, int E) {
    int e = blockIdx.x * blockDim.x + threadIdx.x;
    if (e < E) {
        float nextt = __ldg(&times[E - 1]);
        float tw = expf(-WDECAY * (nextt - __ldg(&times[e])));
        int s = src[e], d = dst[e];
        if (g_qmask[s]) {
            int pos = atomicAdd(&g_cur[s], 1);
            g_adj[pos] = d;
            g_w[pos] = tw;
        }
        if (g_qmask[d]) {
            int pos = atomicAdd(&g_cur[d], 1);
            g_adj[pos] = s;
            g_w[pos] = tw;
        }
    }
}

// ---------------------------------------------------------------------------
// Gather: one block (256 threads = 256 dims) per node. For each masked node:
//   acc_l[n][k] = decay^l * sum_{j in adj(n)} w_j * rp_l[adj_j][k]
// Streaming writes; no atomics; unmasked rows never written (never read).
// ---------------------------------------------------------------------------
__global__ __launch_bounds__(256)
void gather_kernel(const float* __restrict__ rp0,
                   const float* __restrict__ rp1,
                   const float* __restrict__ rp2,
                   const float* __restrict__ times,
                   const float* __restrict__ now_time,
                   int E) {
    const int n = blockIdx.x;
    if (!g_qmask[n]) return;
    const int k = threadIdx.x;

    __shared__ int   s_nb[64];
    __shared__ float s_w[64];

    const int off = g_off[n];
    const int cnt = g_cnt[n];

    float nextt = __ldg(&times[E - 1]);
    float decay = expf(-WDECAY * (nextt - __ldg(&now_time[0])));

    float s0 = 0.f, s1 = 0.f, s2 = 0.f;

    for (int base = 0; base < cnt; base += 64) {
        int m = min(64, cnt - base);
        if (k < m) {
            s_nb[k] = g_adj[off + base + k];
            s_w[k]  = g_w[off + base + k];
        }
        __syncthreads();
        for (int j = 0; j < m; j++) {
            size_t rb = (size_t)s_nb[j] * DDIM + k;
            float w = s_w[j];
            s0 = fmaf(w, __ldg(&rp0[rb]), s0);
            s1 = fmaf(w, __ldg(&rp1[rb]), s1);
            s2 = fmaf(w, __ldg(&rp2[rb]), s2);
        }
        __syncthreads();
    }

    size_t ab = (size_t)n * DDIM + k;
    g_acc[ab]                              = s0;
    g_acc[(size_t)NNODE * DDIM + ab]       = s1 * decay;
    g_acc[2 * (size_t)NNODE * DDIM + ab]   = s2 * (decay * decay);
}

// ---------------------------------------------------------------------------
// Pairwise feature + MLP (unchanged from R4-winning version).
// ---------------------------------------------------------------------------
__global__ __launch_bounds__(256)
void pairwise_kernel(const float* __restrict__ rp0,
                     const float* __restrict__ rp1,
                     const float* __restrict__ rp2,
                     const float* __restrict__ rp3,
                     const float* __restrict__ times,
                     const float* __restrict__ now_time,
                     const float* __restrict__ w1,
                     const float* __restrict__ b1,
                     const float* __restrict__ w2,
                     const float* __restrict__ b2,
                     const int*   __restrict__ qs,
                     const int*   __restrict__ qd,
                     float* __restrict__ out,
                     int B, int E) {
    __shared__ float gram_s[TP * 36];                       // [t][36]
    __shared__ __align__(16) float feat_s[FEAT * TP];       // [f][t], t contiguous
    __shared__ __align__(16) float h_s[HID * 12];           // [j][t] pitch 12 (bank-safe)
    __shared__ float opart[4 * TP * 64];

    const int tid  = threadIdx.x;
    const int lane = tid & 31;
    const int wrp  = tid >> 5;                              // 0..7 == t
    const int pb   = blockIdx.x * TP;
    const int pi   = pb + wrp;

    float nextt = times[E - 1];
    float decay = expf(-WDECAY * (nextt - now_time[0]));
    const float sc1 = decay, sc2 = decay * decay, sc3 = sc2 * decay;
    const float scl[4] = {1.f, sc1, sc2, sc3};

    // ---- Phase 1: per-warp gram (36 symmetric entries) ----
    if (pi < B) {
        int s = qs[pi], d = qd[pi];
        const float4* rp4[4] = {(const float4*)rp0, (const float4*)rp1,
                                (const float4*)rp2, (const float4*)rp3};
        const float4* acc4 = (const float4*)g_acc;

        float g[36];
        #pragma unroll
        for (int i = 0; i < 36; i++) g[i] = 0.f;

        #pragma unroll
        for (int c = 0; c < 2; c++) {
            int cs = (int)(lane * 2 + c);
            float4 v[8];
            #pragma unroll
            for (int l = 0; l < 4; l++) {
                float4 a = rp4[l][(size_t)s * DV4 + cs];
                float4 b = rp4[l][(size_t)d * DV4 + cs];
                a.x *= scl[l]; a.y *= scl[l]; a.z *= scl[l]; a.w *= scl[l];
                b.x *= scl[l]; b.y *= scl[l]; b.z *= scl[l]; b.w *= scl[l];
                if (l > 0) {
                    float4 ea = acc4[(size_t)(l - 1) * NNODE * DV4 + (size_t)s * DV4 + cs];
                    float4 eb = acc4[(size_t)(l - 1) * NNODE * DV4 + (size_t)d * DV4 + cs];
                    a.x += ea.x; a.y += ea.y; a.z += ea.z; a.w += ea.w;
                    b.x += eb.x; b.y += eb.y; b.z += eb.z; b.w += eb.w;
                }
                v[l] = a;
                v[4 + l] = b;
            }
            int idx = 0;
            #pragma unroll
            for (int p = 0; p < 8; p++) {
                #pragma unroll
                for (int q = p; q < 8; q++) {
                    float4 a = v[p], b = v[q];
                    g[idx] = fmaf(a.x, b.x, fmaf(a.y, b.y, fmaf(a.z, b.z, fmaf(a.w, b.w, g[idx]))));
                    idx++;
                }
            }
        }
        // butterfly reduce each entry over lanes
        #pragma unroll
        for (int i = 0; i < 36; i++) {
            #pragma unroll
            for (int st = 16; st > 0; st >>= 1)
                g[i] += __shfl_xor_sync(0xffffffffu, g[i], st);
        }
        #pragma unroll
        for (int i = 0; i < 36; i++) {
            if (lane == (i & 31)) gram_s[wrp * 36 + i] = g[i];
        }
    }
    __syncthreads();

    // ---- Phase 2: log1p + symmetric expand into feat_s[f][t] ----
    for (int e = tid; e < TP * 36; e += 256) {
        int t = e / 36, i = e - t * 36;
        int p = c_p36[i], q = c_q36[i];
        float val = log1pf(fmaxf(gram_s[t * 36 + i], 0.f));
        feat_s[(p * 8 + q) * TP + t] = val;
        feat_s[(q * 8 + p) * TP + t] = val;
    }
    __syncthreads();

    // ---- MLP layer 1 (f32x2 packed over t) ----
    {
        const int j = tid;
        unsigned long long hp0 = 0ull, hp1 = 0ull, hp2 = 0ull, hp3 = 0ull;
        #pragma unroll 4
        for (int f = 0; f < FEAT; f++) {
            const ulonglong2* fp = (const ulonglong2*)(feat_s + f * TP);
            ulonglong2 fa = fp[0];
            ulonglong2 fb = fp[1];
            float w = __ldg(&w1[f * HID + j]);
            unsigned long long ww = pk2(w, w);
            fma2(hp0, fa.x, ww);
            fma2(hp1, fa.y, ww);
            fma2(hp2, fb.x, ww);
            fma2(hp3, fb.y, ww);
        }
        float bb = __ldg(&b1[j]);
        float h0, h1, h2, h3, h4, h5, h6, h7;
        upk2(h0, h1, hp0); upk2(h2, h3, hp1); upk2(h4, h5, hp2); upk2(h6, h7, hp3);
        h0 = fmaxf(h0 + bb, 0.f); h1 = fmaxf(h1 + bb, 0.f);
        h2 = fmaxf(h2 + bb, 0.f); h3 = fmaxf(h3 + bb, 0.f);
        h4 = fmaxf(h4 + bb, 0.f); h5 = fmaxf(h5 + bb, 0.f);
        h6 = fmaxf(h6 + bb, 0.f); h7 = fmaxf(h7 + bb, 0.f);
        float4* hs = (float4*)(h_s + j * 12);
        hs[0] = make_float4(h0, h1, h2, h3);
        hs[1] = make_float4(h4, h5, h6, h7);
    }
    __syncthreads();

    // ---- MLP layer 2 (f32x2 packed over t) ----
    {
        const int fo = tid & 63;
        const int cj = tid >> 6;
        unsigned long long op0 = 0ull, op1 = 0ull, op2 = 0ull, op3 = 0ull;
        #pragma unroll 4
        for (int jj = 0; jj < 64; jj++) {
            int jx = cj * 64 + jj;
            const ulonglong2* hp = (const ulonglong2*)(h_s + jx * 12);
            ulonglong2 ha = hp[0];
            ulonglong2 hb = hp[1];
            float w = __ldg(&w2[jx * FEAT + fo]);
            unsigned long long ww = pk2(w, w);
            fma2(op0, ha.x, ww);
            fma2(op1, ha.y, ww);
            fma2(op2, hb.x, ww);
            fma2(op3, hb.y, ww);
        }
        float o0, o1, o2, o3, o4, o5, o6, o7;
        upk2(o0, o1, op0); upk2(o2, o3, op1); upk2(o4, o5, op2); upk2(o6, o7, op3);
        opart[(cj * TP + 0) * 64 + fo] = o0;
        opart[(cj * TP + 1) * 64 + fo] = o1;
        opart[(cj * TP + 2) * 64 + fo] = o2;
        opart[(cj * TP + 3) * 64 + fo] = o3;
        opart[(cj * TP + 4) * 64 + fo] = o4;
        opart[(cj * TP + 5) * 64 + fo] = o5;
        opart[(cj * TP + 6) * 64 + fo] = o6;
        opart[(cj * TP + 7) * 64 + fo] = o7;
    }
    __syncthreads();

    for (int idx = tid; idx < TP * 64; idx += 256) {
        int t = idx >> 6, ff = idx & 63;
        int po = pb + t;
        if (po < B) {
            float v = __ldg(&b2[ff])
                    + opart[(0 * TP + t) * 64 + ff]
                    + opart[(1 * TP + t) * 64 + ff]
                    + opart[(2 * TP + t) * 64 + ff]
                    + opart[(3 * TP + t) * 64 + ff];
            out[(size_t)po * FEAT + ff] = v;
        }
    }
}

// ---------------------------------------------------------------------------
extern "C" void kernel_launch(void* const* d_in, const int* in_sizes, int n_in,
                              void* d_out, int out_size) {
    const float* rp0  = (const float*)d_in[0];
    const float* rp1  = (const float*)d_in[1];
    const float* rp2  = (const float*)d_in[2];
    const float* rp3  = (const float*)d_in[3];
    const float* times = (const float*)d_in[4];
    const float* nowt  = (const float*)d_in[5];
    const float* w1   = (const float*)d_in[6];
    const float* b1   = (const float*)d_in[7];
    const float* w2   = (const float*)d_in[8];
    const float* b2   = (const float*)d_in[9];
    const int* src    = (const int*)d_in[10];
    const int* dst    = (const int*)d_in[11];
    const int* qsrc   = (const int*)d_in[12];
    const int* qdst   = (const int*)d_in[13];
    float* out = (float*)d_out;

    int E = in_sizes[4];
    int B = in_sizes[12];

    setup_kernel<<<(NNODE + 255) / 256, 256>>>();
    mask_kernel<<<(B + 255) / 256, 256>>>(qsrc, qdst, B);
    hist_kernel<<<(E + 255) / 256, 256>>>(src, dst, E);
    scanA_kernel<<<NB_SCAN, NSCB>>>();
    scanB_kernel<<<1, 32>>>();
    scanC_kernel<<<(NNODE + 255) / 256, 256>>>();
    fill_kernel<<<(E + 255) / 256, 256>>>(src, dst, times, E);

    gather_kernel<<<NNODE, 256>>>(rp0, rp1, rp2, times, nowt, E);

    int pblocks = (B + TP - 1) / TP;
    pairwise_kernel<<<pblocks, 256>>>(rp0, rp1, rp2, rp3, times, nowt,
                                      w1, b1, w2, b2, qsrc, qdst, out, B, E);
}

// round 10
// speedup vs baseline: 1.1970x; 1.0172x over previous
#include <cuda_runtime.h>
#include <math.h>

#define NNODE 100000
#define DDIM  256
#define DV4   64          // DDIM/4
#define NL    3           // accumulated layers 1..3
#define FEAT  64          // pairwise feature dim (8x8)
#define HID   256         // MLP hidden
#define TP    8           // pairs per block in pairwise kernel
#define WDECAY 1e-06f
#define EMAX  200000
#define NSCB  1024        // scan block width
#define NB_SCAN ((NNODE + NSCB - 1) / NSCB)

// Final projections for layers 1..3 (layer 0 == rp0, read directly)
__device__ __align__(16) float g_acc[(size_t)NL * NNODE * DDIM];   // 307 MB
__device__ __align__(16) float g_selfgram[(size_t)NNODE * 12];     // 10 used, pad 12
__device__ unsigned char g_qmask[NNODE];

// CSR adjacency (only masked endpoints get entries)
__device__ int   g_cnt[NNODE];
__device__ int   g_off[NNODE];
__device__ int   g_cur[NNODE];
__device__ int   g_bsum[NB_SCAN + 1];
__device__ int   g_bsumx[NB_SCAN + 1];
__device__ int   g_adj[2 * EMAX];
__device__ float g_w[2 * EMAX];

// map (l,m) in 4x4 to triangular index 0..9
__constant__ int c_tri4[16] = {0,1,2,3, 1,4,5,6, 2,5,7,8, 3,6,8,9};

// ---- packed f32x2 helpers (Blackwell) ----
__device__ __forceinline__ unsigned long long pk2(float a, float b) {
    unsigned long long r;
    asm("mov.b64 %0, {%1,%2};" : "=l"(r) : "f"(a), "f"(b));
    return r;
}
__device__ __forceinline__ void fma2(unsigned long long& d, unsigned long long a, unsigned long long b) {
    asm("fma.rn.f32x2 %0, %1, %2, %0;" : "+l"(d) : "l"(a), "l"(b));
}
__device__ __forceinline__ void upk2(float& lo, float& hi, unsigned long long v) {
    asm("mov.b64 {%0,%1}, %2;" : "=f"(lo), "=f"(hi) : "l"(v));
}

// ---------------------------------------------------------------------------
__global__ void setup_kernel() {
    int i = blockIdx.x * blockDim.x + threadIdx.x;
    if (i < NNODE) { g_qmask[i] = 0; g_cnt[i] = 0; }
}

__global__ void mask_kernel(const int* __restrict__ qs, const int* __restrict__ qd, int B) {
    int i = blockIdx.x * blockDim.x + threadIdx.x;
    if (i < B) {
        g_qmask[qs[i]] = 1;
        g_qmask[qd[i]] = 1;
    }
}

// ---------------------------------------------------------------------------
// CSR build: histogram -> scan -> fill
// ---------------------------------------------------------------------------
__global__ void hist_kernel(const int* __restrict__ src, const int* __restrict__ dst, int E) {
    int e = blockIdx.x * blockDim.x + threadIdx.x;
    if (e < E) {
        int s = src[e], d = dst[e];
        if (g_qmask[s]) atomicAdd(&g_cnt[s], 1);
        if (g_qmask[d]) atomicAdd(&g_cnt[d], 1);
    }
}

__global__ void scanA_kernel() {
    __shared__ int sh[NSCB];
    int tid = threadIdx.x;
    int i = blockIdx.x * NSCB + tid;
    int v = (i < NNODE) ? g_cnt[i] : 0;
    sh[tid] = v;
    __syncthreads();
    #pragma unroll
    for (int st = 1; st < NSCB; st <<= 1) {
        int t = (tid >= st) ? sh[tid - st] : 0;
        __syncthreads();
        sh[tid] += t;
        __syncthreads();
    }
    if (i < NNODE) g_off[i] = sh[tid] - v;     // exclusive within block
    if (tid == NSCB - 1) g_bsum[blockIdx.x] = sh[tid];
}

__global__ void scanB_kernel() {
    if (threadIdx.x == 0 && blockIdx.x == 0) {
        int run = 0;
        for (int b = 0; b < NB_SCAN; b++) {
            int t = g_bsum[b];
            g_bsumx[b] = run;
            run += t;
        }
    }
}

__global__ void scanC_kernel() {
    int i = blockIdx.x * blockDim.x + threadIdx.x;
    if (i < NNODE) {
        int o = g_off[i] + g_bsumx[i >> 10];
        g_off[i] = o;
        g_cur[i] = o;
    }
}

__global__ void fill_kernel(const int* __restrict__ src, const int* __restrict__ dst,
                            const float* __restrict__ times, int E) {
    int e = blockIdx.x * blockDim.x + threadIdx.x;
    if (e < E) {
        float nextt = __ldg(&times[E - 1]);
        float tw = expf(-WDECAY * (nextt - __ldg(&times[e])));
        int s = src[e], d = dst[e];
        if (g_qmask[s]) {
            int pos = atomicAdd(&g_cur[s], 1);
            g_adj[pos] = d;
            g_w[pos] = tw;
        }
        if (g_qmask[d]) {
            int pos = atomicAdd(&g_cur[d], 1);
            g_adj[pos] = s;
            g_w[pos] = tw;
        }
    }
}

// ---------------------------------------------------------------------------
// Gather v2: one block (256 threads = 256 dims) per masked node.
//   proj_l[n][k] = decay^l * rp_l[n][k] + decay^(l-1) * sum_j w_j rp_{l-1}[adj_j][k]
// Writes proj1..3 into g_acc, plus the 10-entry self-gram over (proj0..proj3).
// ---------------------------------------------------------------------------
__global__ __launch_bounds__(256)
void gather_kernel(const float* __restrict__ rp0,
                   const float* __restrict__ rp1,
                   const float* __restrict__ rp2,
                   const float* __restrict__ rp3,
                   const float* __restrict__ times,
                   const float* __restrict__ now_time,
                   int E) {
    const int n = blockIdx.x;
    if (!g_qmask[n]) return;
    const int k = threadIdx.x;

    __shared__ int   s_nb[64];
    __shared__ float s_w[64];
    __shared__ float s_red[8 * 10];

    const int off = g_off[n];
    const int cnt = g_cnt[n];

    float nextt = __ldg(&times[E - 1]);
    float decay = expf(-WDECAY * (nextt - __ldg(&now_time[0])));
    float decay2 = decay * decay;
    float decay3 = decay2 * decay;

    float s0 = 0.f, s1 = 0.f, s2 = 0.f;

    for (int base = 0; base < cnt; base += 64) {
        int m = min(64, cnt - base);
        if (k < m) {
            s_nb[k] = g_adj[off + base + k];
            s_w[k]  = g_w[off + base + k];
        }
        __syncthreads();
        for (int j = 0; j < m; j++) {
            size_t rb = (size_t)s_nb[j] * DDIM + k;
            float w = s_w[j];
            s0 = fmaf(w, __ldg(&rp0[rb]), s0);
            s1 = fmaf(w, __ldg(&rp1[rb]), s1);
            s2 = fmaf(w, __ldg(&rp2[rb]), s2);
        }
        __syncthreads();
    }

    size_t nk = (size_t)n * DDIM + k;
    float p0 = __ldg(&rp0[nk]);
    float p1 = fmaf(decay,  __ldg(&rp1[nk]), s0);
    float p2 = fmaf(decay2, __ldg(&rp2[nk]), s1 * decay);
    float p3 = fmaf(decay3, __ldg(&rp3[nk]), s2 * decay2);

    g_acc[nk]                            = p1;
    g_acc[(size_t)NNODE * DDIM + nk]     = p2;
    g_acc[2 * (size_t)NNODE * DDIM + nk] = p3;

    // self-gram: 10 triangular dots over (p0,p1,p2,p3)
    float t_[10];
    t_[0] = p0 * p0; t_[1] = p0 * p1; t_[2] = p0 * p2; t_[3] = p0 * p3;
    t_[4] = p1 * p1; t_[5] = p1 * p2; t_[6] = p1 * p3;
    t_[7] = p2 * p2; t_[8] = p2 * p3;
    t_[9] = p3 * p3;
    const int lane = k & 31, wrp = k >> 5;
    #pragma unroll
    for (int i = 0; i < 10; i++) {
        #pragma unroll
        for (int st = 16; st > 0; st >>= 1)
            t_[i] += __shfl_xor_sync(0xffffffffu, t_[i], st);
        if (lane == 0) s_red[wrp * 10 + i] = t_[i];
    }
    __syncthreads();
    if (k < 10) {
        float acc = 0.f;
        #pragma unroll
        for (int w = 0; w < 8; w++) acc += s_red[w * 10 + k];
        g_selfgram[(size_t)n * 12 + k] = acc;
    }
}

// ---------------------------------------------------------------------------
// Pairwise v2: warp-per-pair. Cross gram (16 dots) from rp0 + g_acc proj rows;
// self blocks from g_selfgram. Then log1p feat + f32x2 MLP.
// ---------------------------------------------------------------------------
__global__ __launch_bounds__(256)
void pairwise_kernel(const float* __restrict__ rp0,
                     const float* __restrict__ w1,
                     const float* __restrict__ b1,
                     const float* __restrict__ w2,
                     const float* __restrict__ b2,
                     const int*   __restrict__ qs,
                     const int*   __restrict__ qd,
                     float* __restrict__ out,
                     int B) {
    __shared__ float cross_s[TP * 16];                      // [t][16] src_l x dst_m
    __shared__ float sgs_s[TP * 10];                        // src self gram
    __shared__ float sgd_s[TP * 10];                        // dst self gram
    __shared__ __align__(16) float feat_s[FEAT * TP];       // [f][t], t contiguous
    __shared__ __align__(16) float h_s[HID * 12];           // [j][t] pitch 12
    __shared__ float opart[4 * TP * 64];

    const int tid  = threadIdx.x;
    const int lane = tid & 31;
    const int wrp  = tid >> 5;                              // 0..7 == t
    const int pb   = blockIdx.x * TP;
    const int pi   = pb + wrp;

    // ---- Phase 1: per-warp cross gram (16 entries) ----
    if (pi < B) {
        int s = qs[pi], d = qd[pi];
        const float4* rp04 = (const float4*)rp0;
        const float4* acc4 = (const float4*)g_acc;

        float g[16];
        #pragma unroll
        for (int i = 0; i < 16; i++) g[i] = 0.f;

        #pragma unroll
        for (int c = 0; c < 2; c++) {
            int cs = (int)(lane * 2 + c);
            float4 a[4], b[4];
            a[0] = rp04[(size_t)s * DV4 + cs];
            b[0] = rp04[(size_t)d * DV4 + cs];
            #pragma unroll
            for (int l = 1; l < 4; l++) {
                a[l] = acc4[(size_t)(l - 1) * NNODE * DV4 + (size_t)s * DV4 + cs];
                b[l] = acc4[(size_t)(l - 1) * NNODE * DV4 + (size_t)d * DV4 + cs];
            }
            #pragma unroll
            for (int p = 0; p < 4; p++) {
                #pragma unroll
                for (int q = 0; q < 4; q++) {
                    float4 x = a[p], y = b[q];
                    int i = p * 4 + q;
                    g[i] = fmaf(x.x, y.x, fmaf(x.y, y.y, fmaf(x.z, y.z, fmaf(x.w, y.w, g[i]))));
                }
            }
        }
        #pragma unroll
        for (int i = 0; i < 16; i++) {
            #pragma unroll
            for (int st = 16; st > 0; st >>= 1)
                g[i] += __shfl_xor_sync(0xffffffffu, g[i], st);
        }
        #pragma unroll
        for (int i = 0; i < 16; i++) {
            if (lane == i) cross_s[wrp * 16 + i] = g[i];
        }
        // fetch self grams (lanes 0..9 src, 16..25 dst)
        if (lane < 10)                 sgs_s[wrp * 10 + lane]        = g_selfgram[(size_t)s * 12 + lane];
        else if (lane >= 16 && lane < 26) sgd_s[wrp * 10 + (lane - 16)] = g_selfgram[(size_t)d * 12 + (lane - 16)];
    }
    __syncthreads();

    // ---- Phase 2: assemble 8x8 feat with log1p into feat_s[f][t] ----
    #pragma unroll
    for (int e = tid; e < TP * 64; e += 256) {
        int t = e >> 6, p = (e >> 3) & 7, q = e & 7;
        float gv;
        if (p < 4) {
            if (q < 4) gv = sgs_s[t * 10 + c_tri4[p * 4 + q]];
            else       gv = cross_s[t * 16 + p * 4 + (q - 4)];
        } else {
            if (q < 4) gv = cross_s[t * 16 + q * 4 + (p - 4)];
            else       gv = sgd_s[t * 10 + c_tri4[(p - 4) * 4 + (q - 4)]];
        }
        feat_s[(p * 8 + q) * TP + t] = log1pf(fmaxf(gv, 0.f));
    }
    __syncthreads();

    // ---- MLP layer 1 (f32x2 packed over t) ----
    {
        const int j = tid;
        unsigned long long hp0 = 0ull, hp1 = 0ull, hp2 = 0ull, hp3 = 0ull;
        #pragma unroll 4
        for (int f = 0; f < FEAT; f++) {
            const ulonglong2* fp = (const ulonglong2*)(feat_s + f * TP);
            ulonglong2 fa = fp[0];
            ulonglong2 fb = fp[1];
            float w = __ldg(&w1[f * HID + j]);
            unsigned long long ww = pk2(w, w);
            fma2(hp0, fa.x, ww);
            fma2(hp1, fa.y, ww);
            fma2(hp2, fb.x, ww);
            fma2(hp3, fb.y, ww);
        }
        float bb = __ldg(&b1[j]);
        float h0, h1, h2, h3, h4, h5, h6, h7;
        upk2(h0, h1, hp0); upk2(h2, h3, hp1); upk2(h4, h5, hp2); upk2(h6, h7, hp3);
        h0 = fmaxf(h0 + bb, 0.f); h1 = fmaxf(h1 + bb, 0.f);
        h2 = fmaxf(h2 + bb, 0.f); h3 = fmaxf(h3 + bb, 0.f);
        h4 = fmaxf(h4 + bb, 0.f); h5 = fmaxf(h5 + bb, 0.f);
        h6 = fmaxf(h6 + bb, 0.f); h7 = fmaxf(h7 + bb, 0.f);
        float4* hs = (float4*)(h_s + j * 12);
        hs[0] = make_float4(h0, h1, h2, h3);
        hs[1] = make_float4(h4, h5, h6, h7);
    }
    __syncthreads();

    // ---- MLP layer 2 (f32x2 packed over t) ----
    {
        const int fo = tid & 63;
        const int cj = tid >> 6;
        unsigned long long op0 = 0ull, op1 = 0ull, op2 = 0ull, op3 = 0ull;
        #pragma unroll 4
        for (int jj = 0; jj < 64; jj++) {
            int jx = cj * 64 + jj;
            const ulonglong2* hp = (const ulonglong2*)(h_s + jx * 12);
            ulonglong2 ha = hp[0];
            ulonglong2 hb = hp[1];
            float w = __ldg(&w2[jx * FEAT + fo]);
            unsigned long long ww = pk2(w, w);
            fma2(op0, ha.x, ww);
            fma2(op1, ha.y, ww);
            fma2(op2, hb.x, ww);
            fma2(op3, hb.y, ww);
        }
        float o0, o1, o2, o3, o4, o5, o6, o7;
        upk2(o0, o1, op0); upk2(o2, o3, op1); upk2(o4, o5, op2); upk2(o6, o7, op3);
        opart[(cj * TP + 0) * 64 + fo] = o0;
        opart[(cj * TP + 1) * 64 + fo] = o1;
        opart[(cj * TP + 2) * 64 + fo] = o2;
        opart[(cj * TP + 3) * 64 + fo] = o3;
        opart[(cj * TP + 4) * 64 + fo] = o4;
        opart[(cj * TP + 5) * 64 + fo] = o5;
        opart[(cj * TP + 6) * 64 + fo] = o6;
        opart[(cj * TP + 7) * 64 + fo] = o7;
    }
    __syncthreads();

    for (int idx = tid; idx < TP * 64; idx += 256) {
        int t = idx >> 6, ff = idx & 63;
        int po = pb + t;
        if (po < B) {
            float v = __ldg(&b2[ff])
                    + opart[(0 * TP + t) * 64 + ff]
                    + opart[(1 * TP + t) * 64 + ff]
                    + opart[(2 * TP + t) * 64 + ff]
                    + opart[(3 * TP + t) * 64 + ff];
            out[(size_t)po * FEAT + ff] = v;
        }
    }
}

// ---------------------------------------------------------------------------
extern "C" void kernel_launch(void* const* d_in, const int* in_sizes, int n_in,
                              void* d_out, int out_size) {
    const float* rp0  = (const float*)d_in[0];
    const float* rp1  = (const float*)d_in[1];
    const float* rp2  = (const float*)d_in[2];
    const float* rp3  = (const float*)d_in[3];
    const float* times = (const float*)d_in[4];
    const float* nowt  = (const float*)d_in[5];
    const float* w1   = (const float*)d_in[6];
    const float* b1   = (const float*)d_in[7];
    const float* w2   = (const float*)d_in[8];
    const float* b2   = (const float*)d_in[9];
    const int* src    = (const int*)d_in[10];
    const int* dst    = (const int*)d_in[11];
    const int* qsrc   = (const int*)d_in[12];
    const int* qdst   = (const int*)d_in[13];
    float* out = (float*)d_out;

    int E = in_sizes[4];
    int B = in_sizes[12];

    setup_kernel<<<(NNODE + 255) / 256, 256>>>();
    mask_kernel<<<(B + 255) / 256, 256>>>(qsrc, qdst, B);
    hist_kernel<<<(E + 255) / 256, 256>>>(src, dst, E);
    scanA_kernel<<<NB_SCAN, NSCB>>>();
    scanB_kernel<<<1, 32>>>();
    scanC_kernel<<<(NNODE + 255) / 256, 256>>>();
    fill_kernel<<<(E + 255) / 256, 256>>>(src, dst, times, E);

    gather_kernel<<<NNODE, 256>>>(rp0, rp1, rp2, rp3, times, nowt, E);

    int pblocks = (B + TP - 1) / TP;
    pairwise_kernel<<<pblocks, 256>>>(rp0, w1, b1, w2, b2, qsrc, qdst, out, B);
}

// round 14
// speedup vs baseline: 1.4011x; 1.1705x over previous
#include <cuda_runtime.h>
#include <math.h>

#define NNODE 100000
#define DDIM  256
#define DV4   64          // DDIM/4
#define NL    3           // accumulated layers 1..3
#define FEAT  64          // pairwise feature dim (8x8)
#define HID   256         // MLP hidden
#define TP    8           // pairs per block in pairwise kernel
#define WDECAY 1e-06f
#define EMAX  200000
#define NSCB  1024        // scan block width
#define NB_SCAN ((NNODE + NSCB - 1) / NSCB)

// Final projections for layers 1..3 (layer 0 == rp0, read directly)
__device__ __align__(16) float g_acc[(size_t)NL * NNODE * DDIM];   // 307 MB
__device__ __align__(16) float g_selfgram[(size_t)NNODE * 12];     // 10 used, pad 12
__device__ unsigned char g_qmask[NNODE];

// CSR adjacency (only masked endpoints get entries)
__device__ int   g_cnt[NNODE];
__device__ int   g_off[NNODE];
__device__ int   g_cur[NNODE];
__device__ int   g_scan_total;
__device__ int   g_adj[2 * EMAX];
__device__ float g_w[2 * EMAX];

// map (l,m) in 4x4 to triangular index 0..9
__constant__ int c_tri4[16] = {0,1,2,3, 1,4,5,6, 2,5,7,8, 3,6,8,9};

// ---- packed f32x2 helpers (Blackwell) ----
__device__ __forceinline__ unsigned long long pk2(float a, float b) {
    unsigned long long r;
    asm("mov.b64 %0, {%1,%2};" : "=l"(r) : "f"(a), "f"(b));
    return r;
}
__device__ __forceinline__ void fma2(unsigned long long& d, unsigned long long a, unsigned long long b) {
    asm("fma.rn.f32x2 %0, %1, %2, %0;" : "+l"(d) : "l"(a), "l"(b));
}
__device__ __forceinline__ void upk2(float& lo, float& hi, unsigned long long v) {
    asm("mov.b64 {%0,%1}, %2;" : "=f"(lo), "=f"(hi) : "l"(v));
}

__device__ __forceinline__ void fma4(float4& acc, float w, float4 v) {
    acc.x = fmaf(w, v.x, acc.x);
    acc.y = fmaf(w, v.y, acc.y);
    acc.z = fmaf(w, v.z, acc.z);
    acc.w = fmaf(w, v.w, acc.w);
}
__device__ __forceinline__ float dot8(float4 xa, float4 xb, float4 ya, float4 yb) {
    float s = xa.x * ya.x;
    s = fmaf(xa.y, ya.y, s); s = fmaf(xa.z, ya.z, s); s = fmaf(xa.w, ya.w, s);
    s = fmaf(xb.x, yb.x, s); s = fmaf(xb.y, yb.y, s);
    s = fmaf(xb.z, yb.z, s); s = fmaf(xb.w, yb.w, s);
    return s;
}

// ---------------------------------------------------------------------------
// Launch 1: setup — clear qmask, counters, scan total
// ---------------------------------------------------------------------------
__global__ void setup_kernel() {
    int i = blockIdx.x * blockDim.x + threadIdx.x;
    if (i < NNODE) { g_qmask[i] = 0; g_cnt[i] = 0; }
    if (i == 0) g_scan_total = 0;
}

// Launch 2
__global__ void mask_kernel(const int* __restrict__ qs, const int* __restrict__ qd, int B) {
    int i = blockIdx.x * blockDim.x + threadIdx.x;
    if (i < B) {
        g_qmask[qs[i]] = 1;
        g_qmask[qd[i]] = 1;
    }
}

// Launch 3
__global__ void hist_kernel(const int* __restrict__ src, const int* __restrict__ dst, int E) {
    int e = blockIdx.x * blockDim.x + threadIdx.x;
    if (e < E) {
        int s = src[e], d = dst[e];
        if (g_qmask[s]) atomicAdd(&g_cnt[s], 1);
        if (g_qmask[d]) atomicAdd(&g_cnt[d], 1);
    }
}

// ---------------------------------------------------------------------------
// Launch 4: single-pass scan. Block base via atomicAdd (offset values are
// run-order dependent but always valid disjoint ranges; per-node adjacency
// ordering is already nondeterministic via fill's atomics).
// ---------------------------------------------------------------------------
__global__ void scan_kernel() {
    __shared__ int sh[NSCB];
    __shared__ int s_base;
    int tid = threadIdx.x;
    int i = blockIdx.x * NSCB + tid;
    int v = (i < NNODE) ? g_cnt[i] : 0;
    sh[tid] = v;
    __syncthreads();
    #pragma unroll
    for (int st = 1; st < NSCB; st <<= 1) {
        int t = (tid >= st) ? sh[tid - st] : 0;
        __syncthreads();
        sh[tid] += t;
        __syncthreads();
    }
    if (tid == NSCB - 1) s_base = atomicAdd(&g_scan_total, sh[tid]);
    __syncthreads();
    if (i < NNODE) {
        int o = s_base + sh[tid] - v;   // exclusive prefix + block base
        g_off[i] = o;
        g_cur[i] = o;
    }
}

// Launch 5
__global__ void fill_kernel(const int* __restrict__ src, const int* __restrict__ dst,
                            const float* __restrict__ times, int E) {
    int e = blockIdx.x * blockDim.x + threadIdx.x;
    if (e < E) {
        float nextt = __ldg(&times[E - 1]);
        float tw = expf(-WDECAY * (nextt - __ldg(&times[e])));
        int s = src[e], d = dst[e];
        if (g_qmask[s]) {
            int pos = atomicAdd(&g_cur[s], 1);
            g_adj[pos] = d;
            g_w[pos] = tw;
        }
        if (g_qmask[d]) {
            int pos = atomicAdd(&g_cur[d], 1);
            g_adj[pos] = s;
            g_w[pos] = tw;
        }
    }
}

// ---------------------------------------------------------------------------
// Launch 6 (ncu-captured): gather v3 — warp per node, lane owns 8 dims
// (2 float4). Registers only, no smem, neighbor loop unrolled x2 for MLP.
//   proj_l[n] = decay^l * rp_l[n] + decay^(l-1) * sum_j w_j rp_{l-1}[adj_j]
// Writes proj1..3 to g_acc and the 10-entry self-gram to g_selfgram.
// ---------------------------------------------------------------------------
__global__ __launch_bounds__(256)
void gather_kernel(const float* __restrict__ rp0,
                   const float* __restrict__ rp1,
                   const float* __restrict__ rp2,
                   const float* __restrict__ rp3,
                   const float* __restrict__ times,
                   const float* __restrict__ now_time,
                   int E) {
    const int gw   = (blockIdx.x * blockDim.x + threadIdx.x) >> 5;
    const int lane = threadIdx.x & 31;
    if (gw >= NNODE) return;
    const int n = gw;
    if (!g_qmask[n]) return;

    const int off = g_off[n];
    const int cnt = g_cnt[n];
    const int c0  = lane * 2;            // this lane's float4 pair within a row

    float nextt = __ldg(&times[E - 1]);
    float decay = expf(-WDECAY * (nextt - __ldg(&now_time[0])));
    float decay2 = decay * decay;
    float decay3 = decay2 * decay;

    const float4* r0 = (const float4*)rp0;
    const float4* r1 = (const float4*)rp1;
    const float4* r2 = (const float4*)rp2;

    float4 z = make_float4(0.f, 0.f, 0.f, 0.f);
    float4 a0a = z, a0b = z, a1a = z, a1b = z, a2a = z, a2b = z;

    int j = 0;
    for (; j + 2 <= cnt; j += 2) {
        int   nbA = __ldg(&g_adj[off + j]);
        float wA  = __ldg(&g_w[off + j]);
        int   nbB = __ldg(&g_adj[off + j + 1]);
        float wB  = __ldg(&g_w[off + j + 1]);
        size_t bA = (size_t)nbA * DV4 + c0;
        size_t bB = (size_t)nbB * DV4 + c0;
        float4 xA0a = r0[bA],     xB0a = r0[bB];
        float4 xA0b = r0[bA + 1], xB0b = r0[bB + 1];
        float4 xA1a = r1[bA],     xB1a = r1[bB];
        float4 xA1b = r1[bA + 1], xB1b = r1[bB + 1];
        float4 xA2a = r2[bA],     xB2a = r2[bB];
        float4 xA2b = r2[bA + 1], xB2b = r2[bB + 1];
        fma4(a0a, wA, xA0a); fma4(a0b, wA, xA0b);
        fma4(a1a, wA, xA1a); fma4(a1b, wA, xA1b);
        fma4(a2a, wA, xA2a); fma4(a2b, wA, xA2b);
        fma4(a0a, wB, xB0a); fma4(a0b, wB, xB0b);
        fma4(a1a, wB, xB1a); fma4(a1b, wB, xB1b);
        fma4(a2a, wB, xB2a); fma4(a2b, wB, xB2b);
    }
    if (j < cnt) {
        int   nb = __ldg(&g_adj[off + j]);
        float w  = __ldg(&g_w[off + j]);
        size_t b = (size_t)nb * DV4 + c0;
        fma4(a0a, w, r0[b]); fma4(a0b, w, r0[b + 1]);
        fma4(a1a, w, r1[b]); fma4(a1b, w, r1[b + 1]);
        fma4(a2a, w, r2[b]); fma4(a2b, w, r2[b + 1]);
    }

    // own rows -> final projections
    size_t nb4 = (size_t)n * DV4 + c0;
    float4 p0a = r0[nb4], p0b = r0[nb4 + 1];
    float4 p1a = r1[nb4], p1b = r1[nb4 + 1];
    float4 p2a = r2[nb4], p2b = r2[nb4 + 1];
    float4 p3a = ((const float4*)rp3)[nb4], p3b = ((const float4*)rp3)[nb4 + 1];

    // p1 = decay*rp1 + a0 ; p2 = decay2*rp2 + decay*a1 ; p3 = decay3*rp3 + decay2*a2
    p1a.x = fmaf(decay, p1a.x, a0a.x); p1a.y = fmaf(decay, p1a.y, a0a.y);
    p1a.z = fmaf(decay, p1a.z, a0a.z); p1a.w = fmaf(decay, p1a.w, a0a.w);
    p1b.x = fmaf(decay, p1b.x, a0b.x); p1b.y = fmaf(decay, p1b.y, a0b.y);
    p1b.z = fmaf(decay, p1b.z, a0b.z); p1b.w = fmaf(decay, p1b.w, a0b.w);

    p2a.x = fmaf(decay2, p2a.x, decay * a1a.x); p2a.y = fmaf(decay2, p2a.y, decay * a1a.y);
    p2a.z = fmaf(decay2, p2a.z, decay * a1a.z); p2a.w = fmaf(decay2, p2a.w, decay * a1a.w);
    p2b.x = fmaf(decay2, p2b.x, decay * a1b.x); p2b.y = fmaf(decay2, p2b.y, decay * a1b.y);
    p2b.z = fmaf(decay2, p2b.z, decay * a1b.z); p2b.w = fmaf(decay2, p2b.w, decay * a1b.w);

    p3a.x = fmaf(decay3, p3a.x, decay2 * a2a.x); p3a.y = fmaf(decay3, p3a.y, decay2 * a2a.y);
    p3a.z = fmaf(decay3, p3a.z, decay2 * a2a.z); p3a.w = fmaf(decay3, p3a.w, decay2 * a2a.w);
    p3b.x = fmaf(decay3, p3b.x, decay2 * a2b.x); p3b.y = fmaf(decay3, p3b.y, decay2 * a2b.y);
    p3b.z = fmaf(decay3, p3b.z, decay2 * a2b.z); p3b.w = fmaf(decay3, p3b.w, decay2 * a2b.w);

    float4* acc4 = (float4*)g_acc;
    acc4[nb4] = p1a;                               acc4[nb4 + 1] = p1b;
    acc4[(size_t)NNODE * DV4 + nb4] = p2a;         acc4[(size_t)NNODE * DV4 + nb4 + 1] = p2b;
    acc4[2 * (size_t)NNODE * DV4 + nb4] = p3a;     acc4[2 * (size_t)NNODE * DV4 + nb4 + 1] = p3b;

    // self-gram: 10 triangular dots, per-lane partials over 8 dims
    float t_[10];
    t_[0] = dot8(p0a, p0b, p0a, p0b);
    t_[1] = dot8(p0a, p0b, p1a, p1b);
    t_[2] = dot8(p0a, p0b, p2a, p2b);
    t_[3] = dot8(p0a, p0b, p3a, p3b);
    t_[4] = dot8(p1a, p1b, p1a, p1b);
    t_[5] = dot8(p1a, p1b, p2a, p2b);
    t_[6] = dot8(p1a, p1b, p3a, p3b);
    t_[7] = dot8(p2a, p2b, p2a, p2b);
    t_[8] = dot8(p2a, p2b, p3a, p3b);
    t_[9] = dot8(p3a, p3b, p3a, p3b);
    #pragma unroll
    for (int i = 0; i < 10; i++) {
        #pragma unroll
        for (int st = 16; st > 0; st >>= 1)
            t_[i] += __shfl_xor_sync(0xffffffffu, t_[i], st);
    }
    if (lane < 10) {
        float v = t_[0];
        #pragma unroll
        for (int i = 1; i < 10; i++) if (lane == i) v = t_[i];
        g_selfgram[(size_t)n * 12 + lane] = v;
    }
}

// ---------------------------------------------------------------------------
// Launch 7: pairwise (unchanged from R10).
// ---------------------------------------------------------------------------
__global__ __launch_bounds__(256)
void pairwise_kernel(const float* __restrict__ rp0,
                     const float* __restrict__ w1,
                     const float* __restrict__ b1,
                     const float* __restrict__ w2,
                     const float* __restrict__ b2,
                     const int*   __restrict__ qs,
                     const int*   __restrict__ qd,
                     float* __restrict__ out,
                     int B) {
    __shared__ float cross_s[TP * 16];                      // [t][16] src_l x dst_m
    __shared__ float sgs_s[TP * 10];                        // src self gram
    __shared__ float sgd_s[TP * 10];                        // dst self gram
    __shared__ __align__(16) float feat_s[FEAT * TP];       // [f][t], t contiguous
    __shared__ __align__(16) float h_s[HID * 12];           // [j][t] pitch 12
    __shared__ float opart[4 * TP * 64];

    const int tid  = threadIdx.x;
    const int lane = tid & 31;
    const int wrp  = tid >> 5;                              // 0..7 == t
    const int pb   = blockIdx.x * TP;
    const int pi   = pb + wrp;

    // ---- Phase 1: per-warp cross gram (16 entries) ----
    if (pi < B) {
        int s = qs[pi], d = qd[pi];
        const float4* rp04 = (const float4*)rp0;
        const float4* acc4 = (const float4*)g_acc;

        float g[16];
        #pragma unroll
        for (int i = 0; i < 16; i++) g[i] = 0.f;

        #pragma unroll
        for (int c = 0; c < 2; c++) {
            int cs = (int)(lane * 2 + c);
            float4 a[4], b[4];
            a[0] = rp04[(size_t)s * DV4 + cs];
            b[0] = rp04[(size_t)d * DV4 + cs];
            #pragma unroll
            for (int l = 1; l < 4; l++) {
                a[l] = acc4[(size_t)(l - 1) * NNODE * DV4 + (size_t)s * DV4 + cs];
                b[l] = acc4[(size_t)(l - 1) * NNODE * DV4 + (size_t)d * DV4 + cs];
            }
            #pragma unroll
            for (int p = 0; p < 4; p++) {
                #pragma unroll
                for (int q = 0; q < 4; q++) {
                    float4 x = a[p], y = b[q];
                    int i = p * 4 + q;
                    g[i] = fmaf(x.x, y.x, fmaf(x.y, y.y, fmaf(x.z, y.z, fmaf(x.w, y.w, g[i]))));
                }
            }
        }
        #pragma unroll
        for (int i = 0; i < 16; i++) {
            #pragma unroll
            for (int st = 16; st > 0; st >>= 1)
                g[i] += __shfl_xor_sync(0xffffffffu, g[i], st);
        }
        #pragma unroll
        for (int i = 0; i < 16; i++) {
            if (lane == i) cross_s[wrp * 16 + i] = g[i];
        }
        // fetch self grams (lanes 0..9 src, 16..25 dst)
        if (lane < 10)                 sgs_s[wrp * 10 + lane]        = g_selfgram[(size_t)s * 12 + lane];
        else if (lane >= 16 && lane < 26) sgd_s[wrp * 10 + (lane - 16)] = g_selfgram[(size_t)d * 12 + (lane - 16)];
    }
    __syncthreads();

    // ---- Phase 2: assemble 8x8 feat with log1p into feat_s[f][t] ----
    #pragma unroll
    for (int e = tid; e < TP * 64; e += 256) {
        int t = e >> 6, p = (e >> 3) & 7, q = e & 7;
        float gv;
        if (p < 4) {
            if (q < 4) gv = sgs_s[t * 10 + c_tri4[p * 4 + q]];
            else       gv = cross_s[t * 16 + p * 4 + (q - 4)];
        } else {
            if (q < 4) gv = cross_s[t * 16 + q * 4 + (p - 4)];
            else       gv = sgd_s[t * 10 + c_tri4[(p - 4) * 4 + (q - 4)]];
        }
        feat_s[(p * 8 + q) * TP + t] = log1pf(fmaxf(gv, 0.f));
    }
    __syncthreads();

    // ---- MLP layer 1 (f32x2 packed over t) ----
    {
        const int j = tid;
        unsigned long long hp0 = 0ull, hp1 = 0ull, hp2 = 0ull, hp3 = 0ull;
        #pragma unroll 4
        for (int f = 0; f < FEAT; f++) {
            const ulonglong2* fp = (const ulonglong2*)(feat_s + f * TP);
            ulonglong2 fa = fp[0];
            ulonglong2 fb = fp[1];
            float w = __ldg(&w1[f * HID + j]);
            unsigned long long ww = pk2(w, w);
            fma2(hp0, fa.x, ww);
            fma2(hp1, fa.y, ww);
            fma2(hp2, fb.x, ww);
            fma2(hp3, fb.y, ww);
        }
        float bb = __ldg(&b1[j]);
        float h0, h1, h2, h3, h4, h5, h6, h7;
        upk2(h0, h1, hp0); upk2(h2, h3, hp1); upk2(h4, h5, hp2); upk2(h6, h7, hp3);
        h0 = fmaxf(h0 + bb, 0.f); h1 = fmaxf(h1 + bb, 0.f);
        h2 = fmaxf(h2 + bb, 0.f); h3 = fmaxf(h3 + bb, 0.f);
        h4 = fmaxf(h4 + bb, 0.f); h5 = fmaxf(h5 + bb, 0.f);
        h6 = fmaxf(h6 + bb, 0.f); h7 = fmaxf(h7 + bb, 0.f);
        float4* hs = (float4*)(h_s + j * 12);
        hs[0] = make_float4(h0, h1, h2, h3);
        hs[1] = make_float4(h4, h5, h6, h7);
    }
    __syncthreads();

    // ---- MLP layer 2 (f32x2 packed over t) ----
    {
        const int fo = tid & 63;
        const int cj = tid >> 6;
        unsigned long long op0 = 0ull, op1 = 0ull, op2 = 0ull, op3 = 0ull;
        #pragma unroll 4
        for (int jj = 0; jj < 64; jj++) {
            int jx = cj * 64 + jj;
            const ulonglong2* hp = (const ulonglong2*)(h_s + jx * 12);
            ulonglong2 ha = hp[0];
            ulonglong2 hb = hp[1];
            float w = __ldg(&w2[jx * FEAT + fo]);
            unsigned long long ww = pk2(w, w);
            fma2(op0, ha.x, ww);
            fma2(op1, ha.y, ww);
            fma2(op2, hb.x, ww);
            fma2(op3, hb.y, ww);
        }
        float o0, o1, o2, o3, o4, o5, o6, o7;
        upk2(o0, o1, op0); upk2(o2, o3, op1); upk2(o4, o5, op2); upk2(o6, o7, op3);
        opart[(cj * TP + 0) * 64 + fo] = o0;
        opart[(cj * TP + 1) * 64 + fo] = o1;
        opart[(cj * TP + 2) * 64 + fo] = o2;
        opart[(cj * TP + 3) * 64 + fo] = o3;
        opart[(cj * TP + 4) * 64 + fo] = o4;
        opart[(cj * TP + 5) * 64 + fo] = o5;
        opart[(cj * TP + 6) * 64 + fo] = o6;
        opart[(cj * TP + 7) * 64 + fo] = o7;
    }
    __syncthreads();

    for (int idx = tid; idx < TP * 64; idx += 256) {
        int t = idx >> 6, ff = idx & 63;
        int po = pb + t;
        if (po < B) {
            float v = __ldg(&b2[ff])
                    + opart[(0 * TP + t) * 64 + ff]
                    + opart[(1 * TP + t) * 64 + ff]
                    + opart[(2 * TP + t) * 64 + ff]
                    + opart[(3 * TP + t) * 64 + ff];
            out[(size_t)po * FEAT + ff] = v;
        }
    }
}

// ---------------------------------------------------------------------------
extern "C" void kernel_launch(void* const* d_in, const int* in_sizes, int n_in,
                              void* d_out, int out_size) {
    const float* rp0  = (const float*)d_in[0];
    const float* rp1  = (const float*)d_in[1];
    const float* rp2  = (const float*)d_in[2];
    const float* rp3  = (const float*)d_in[3];
    const float* times = (const float*)d_in[4];
    const float* nowt  = (const float*)d_in[5];
    const float* w1   = (const float*)d_in[6];
    const float* b1   = (const float*)d_in[7];
    const float* w2   = (const float*)d_in[8];
    const float* b2   = (const float*)d_in[9];
    const int* src    = (const int*)d_in[10];
    const int* dst    = (const int*)d_in[11];
    const int* qsrc   = (const int*)d_in[12];
    const int* qdst   = (const int*)d_in[13];
    float* out = (float*)d_out;

    int E = in_sizes[4];
    int B = in_sizes[12];

    setup_kernel<<<(NNODE + 255) / 256, 256>>>();                      // 1
    mask_kernel<<<(B + 255) / 256, 256>>>(qsrc, qdst, B);              // 2
    hist_kernel<<<(E + 255) / 256, 256>>>(src, dst, E);                // 3
    scan_kernel<<<NB_SCAN, NSCB>>>();                                  // 4
    fill_kernel<<<(E + 255) / 256, 256>>>(src, dst, times, E);         // 5

    int gblocks = (NNODE * 32 + 255) / 256;                            // warp per node
    gather_kernel<<<gblocks, 256>>>(rp0, rp1, rp2, rp3, times, nowt, E);  // 6 (profiled)

    int pblocks = (B + TP - 1) / TP;
    pairwise_kernel<<<pblocks, 256>>>(rp0, w1, b1, w2, b2, qsrc, qdst, out, B);  // 7
}